// round 3
// baseline (speedup 1.0000x reference)
#include <cuda_runtime.h>
#include <math.h>

#define N_NODES     500000
#define HIDDEN      256
#define NUM_CLASSES 104
#define AUX_DIM     2
#define NUM_GRAPHS  2048
#define D_IN        (NUM_CLASSES + AUX_DIM)   // 106
#define GRAPH_X     128
#define CP          128                        // padded class dim
#define KB          32                         // K chunk
#define TM          64                         // node tile

// ---------------- device scratch (no allocations allowed) ----------------
__device__ float g_Wg_pad[2 * HIDDEN * CP];    // [512][128]
__device__ float g_Wt_pad[HIDDEN * CP];        // [256][128]
__device__ float g_bg_pad[CP];
__device__ float g_bt_pad[CP];
__device__ int   g_start[NUM_GRAPHS + 1];
__device__ float g_readout[NUM_GRAPHS * NUM_CLASSES];

// ---------------- prep: pad weights 104 -> 128 classes ----------------
__global__ void prep_kernel(const float* __restrict__ Wg, const float* __restrict__ bg,
                            const float* __restrict__ Wt, const float* __restrict__ bt) {
    int i = blockIdx.x * blockDim.x + threadIdx.x;
    int total = 2 * HIDDEN * CP;
    if (i < total) {
        int k = i / CP, c = i % CP;
        g_Wg_pad[i] = (c < NUM_CLASSES) ? Wg[k * NUM_CLASSES + c] : 0.f;
        if (k < HIDDEN)
            g_Wt_pad[i] = (c < NUM_CLASSES) ? Wt[k * NUM_CLASSES + c] : 0.f;
    }
    if (i < CP) {
        g_bg_pad[i] = (i < NUM_CLASSES) ? bg[i] : 0.f;
        g_bt_pad[i] = (i < NUM_CLASSES) ? bt[i] : 0.f;
    }
}

// ---------------- graph segment starts via binary search (sorted ids) ----------------
__global__ void starts_kernel(const int* __restrict__ gl, int n) {
    int g = blockIdx.x * blockDim.x + threadIdx.x;
    if (g > NUM_GRAPHS) return;
    int lo = 0, hi = n;
    while (lo < hi) {
        int mid = (lo + hi) >> 1;
        if (gl[mid] < g) lo = mid + 1; else hi = mid;
    }
    g_start[g] = lo;
}

// ---------------- main fused kernel: one block per graph ----------------
// Computes sigmoid([xi|xf] @ Wg + bg) * (xf @ Wt + bt) per node, reduced
// over the graph's contiguous node range -> g_readout[g][:104]. No atomics
// to global memory; per-class running sum lives in smem.
__global__ __launch_bounds__(256, 2) void fused_node_kernel(
        const float* __restrict__ xi, const float* __restrict__ xf) {
    __shared__ float sA[TM][KB];       // 8 KB   node-feature tile
    __shared__ float sWg[KB][CP];      // 16 KB  gate-weight chunk
    __shared__ float sWt[KB][CP];      // 16 KB  transform-weight chunk
    __shared__ float sAcc[CP];         // per-class running sum for this graph

    const int g = blockIdx.x;
    const int s = g_start[g], e = g_start[g + 1];
    const int tid = threadIdx.x;
    const int tx = tid & 31;           // column group lane
    const int ty = tid >> 5;           // row group (0..7)

    if (tid < CP) sAcc[tid] = 0.f;
    __syncthreads();

    for (int t0 = s; t0 < e; t0 += TM) {
        int cnt = e - t0; if (cnt > TM) cnt = TM;

        float accG[8][4];
        float accT[8][4];
        #pragma unroll
        for (int i = 0; i < 8; i++)
            #pragma unroll
            for (int j = 0; j < 4; j++) { accG[i][j] = 0.f; accT[i][j] = 0.f; }

        // ---- pass 1: K over initial states (gate first half) ----
        for (int k0 = 0; k0 < HIDDEN; k0 += KB) {
            __syncthreads();
            // load A tile (64 x 32) as float4, zero-fill past cnt
            for (int l = tid; l < TM * 8; l += 256) {
                int r = l >> 3, q = l & 7;
                float4 v = make_float4(0.f, 0.f, 0.f, 0.f);
                if (r < cnt)
                    v = *(const float4*)(xi + (size_t)(t0 + r) * HIDDEN + k0 + q * 4);
                sA[r][q * 4 + 0] = v.x; sA[r][q * 4 + 1] = v.y;
                sA[r][q * 4 + 2] = v.z; sA[r][q * 4 + 3] = v.w;
            }
            {
                const float4* wg4 = (const float4*)(g_Wg_pad + k0 * CP);
                float4* dWg = (float4*)&sWg[0][0];
                for (int l = tid; l < KB * CP / 4; l += 256) dWg[l] = wg4[l];
            }
            __syncthreads();
            #pragma unroll 4
            for (int k = 0; k < KB; k++) {
                float a[8];
                #pragma unroll
                for (int i = 0; i < 8; i++) a[i] = sA[ty * 8 + i][k];
                float wg[4];
                #pragma unroll
                for (int j = 0; j < 4; j++) wg[j] = sWg[k][tx + 32 * j];
                #pragma unroll
                for (int i = 0; i < 8; i++)
                    #pragma unroll
                    for (int j = 0; j < 4; j++)
                        accG[i][j] = fmaf(a[i], wg[j], accG[i][j]);
            }
        }

        // ---- pass 2: K over final states (gate second half + transform) ----
        for (int k0 = 0; k0 < HIDDEN; k0 += KB) {
            __syncthreads();
            for (int l = tid; l < TM * 8; l += 256) {
                int r = l >> 3, q = l & 7;
                float4 v = make_float4(0.f, 0.f, 0.f, 0.f);
                if (r < cnt)
                    v = *(const float4*)(xf + (size_t)(t0 + r) * HIDDEN + k0 + q * 4);
                sA[r][q * 4 + 0] = v.x; sA[r][q * 4 + 1] = v.y;
                sA[r][q * 4 + 2] = v.z; sA[r][q * 4 + 3] = v.w;
            }
            {
                const float4* wg4 = (const float4*)(g_Wg_pad + (HIDDEN + k0) * CP);
                float4* dWg = (float4*)&sWg[0][0];
                for (int l = tid; l < KB * CP / 4; l += 256) dWg[l] = wg4[l];
                const float4* wt4 = (const float4*)(g_Wt_pad + k0 * CP);
                float4* dWt = (float4*)&sWt[0][0];
                for (int l = tid; l < KB * CP / 4; l += 256) dWt[l] = wt4[l];
            }
            __syncthreads();
            #pragma unroll 4
            for (int k = 0; k < KB; k++) {
                float a[8];
                #pragma unroll
                for (int i = 0; i < 8; i++) a[i] = sA[ty * 8 + i][k];
                float wg[4], wt[4];
                #pragma unroll
                for (int j = 0; j < 4; j++) wg[j] = sWg[k][tx + 32 * j];
                #pragma unroll
                for (int j = 0; j < 4; j++) wt[j] = sWt[k][tx + 32 * j];
                #pragma unroll
                for (int i = 0; i < 8; i++)
                    #pragma unroll
                    for (int j = 0; j < 4; j++) {
                        accG[i][j] = fmaf(a[i], wg[j], accG[i][j]);
                        accT[i][j] = fmaf(a[i], wt[j], accT[i][j]);
                    }
            }
        }

        // ---- epilogue: sigmoid * transform, reduce over rows of this tile ----
        #pragma unroll
        for (int j = 0; j < 4; j++) {
            int c = tx + 32 * j;
            float bgc = g_bg_pad[c], btc = g_bt_pad[c];
            float part = 0.f;
            #pragma unroll
            for (int i = 0; i < 8; i++) {
                int r = ty * 8 + i;
                if (r < cnt) {
                    float sig = 1.f / (1.f + expf(-(accG[i][j] + bgc)));
                    part += sig * (accT[i][j] + btc);
                }
            }
            atomicAdd(&sAcc[c], part);
        }
    }

    __syncthreads();
    if (tid < NUM_CLASSES) g_readout[g * NUM_CLASSES + tid] = sAcc[tid];
}

// ---------------- BN + MLP: one block (128 thr) per graph ----------------
__global__ void mlp_kernel(const float* __restrict__ aux,
                           const float* __restrict__ bn_gamma, const float* __restrict__ bn_beta,
                           const float* __restrict__ bn_mean,  const float* __restrict__ bn_var,
                           const float* __restrict__ W1, const float* __restrict__ b1,
                           const float* __restrict__ W2, const float* __restrict__ b2,
                           float* __restrict__ out) {
    __shared__ float sn[D_IN];
    __shared__ float sh[GRAPH_X];
    int g = blockIdx.x, tid = threadIdx.x;
    if (tid < D_IN) {
        float v = (tid < NUM_CLASSES) ? g_readout[g * NUM_CLASSES + tid]
                                      : aux[g * AUX_DIM + (tid - NUM_CLASSES)];
        sn[tid] = (v - bn_mean[tid]) * rsqrtf(bn_var[tid] + 1e-5f) * bn_gamma[tid] + bn_beta[tid];
    }
    __syncthreads();
    {
        float acc = b1[tid];
        #pragma unroll 2
        for (int d = 0; d < D_IN; d++) acc = fmaf(sn[d], W1[d * GRAPH_X + tid], acc);
        sh[tid] = fmaxf(acc, 0.f);
    }
    __syncthreads();
    if (tid < NUM_CLASSES) {
        float acc = b2[tid];
        #pragma unroll 4
        for (int j = 0; j < GRAPH_X; j++) acc = fmaf(sh[j], W2[j * NUM_CLASSES + tid], acc);
        out[g * NUM_CLASSES + tid] = acc;
    }
}

// ---------------- launch ----------------
extern "C" void kernel_launch(void* const* d_in, const int* in_sizes, int n_in,
                              void* d_out, int out_size) {
    // input order: xi, xf, aux, graph_ids, [num_graphs scalar?], Wg, bg, Wt, bt,
    //              bn_gamma, bn_beta, bn_mean, bn_var, W1, b1, W2, b2
    int o = (n_in > 4 && in_sizes[4] == 1) ? 1 : 0;   // skip num_graphs scalar if present
    const float* xi  = (const float*)d_in[0];
    const float* xf  = (const float*)d_in[1];
    const float* aux = (const float*)d_in[2];
    const int*   gl  = (const int*)  d_in[3];
    const float* Wg  = (const float*)d_in[4 + o];
    const float* bg  = (const float*)d_in[5 + o];
    const float* Wt  = (const float*)d_in[6 + o];
    const float* bt  = (const float*)d_in[7 + o];
    const float* bn_gamma = (const float*)d_in[8 + o];
    const float* bn_beta  = (const float*)d_in[9 + o];
    const float* bn_mean  = (const float*)d_in[10 + o];
    const float* bn_var   = (const float*)d_in[11 + o];
    const float* W1 = (const float*)d_in[12 + o];
    const float* b1 = (const float*)d_in[13 + o];
    const float* W2 = (const float*)d_in[14 + o];
    const float* b2 = (const float*)d_in[15 + o];
    float* out = (float*)d_out;

    prep_kernel<<<(2 * HIDDEN * CP + 255) / 256, 256>>>(Wg, bg, Wt, bt);
    starts_kernel<<<(NUM_GRAPHS + 1 + 255) / 256, 256>>>(gl, N_NODES);
    fused_node_kernel<<<NUM_GRAPHS, 256>>>(xi, xf);
    mlp_kernel<<<NUM_GRAPHS, GRAPH_X>>>(aux, bn_gamma, bn_beta, bn_mean, bn_var,
                                        W1, b1, W2, b2, out);
}

// round 7
// speedup vs baseline: 3.3526x; 3.3526x over previous
#include <cuda_runtime.h>
#include <cstdint>
#include <math.h>

#define N_NODES     500000
#define HIDDEN      256
#define NUM_CLASSES 104
#define AUX_DIM     2
#define NUM_GRAPHS  2048
#define D_IN        (NUM_CLASSES + AUX_DIM)   // 106
#define GRAPH_X     128
#define CP          128                        // padded class dim

// smem tile geometry (floats)
#define SA_STRIDE   36                         // 128 x 32 A tile, padded
#define SW_STRIDE   136                        // 32 x 128 W tile, padded
#define A_FLOATS    (128 * SA_STRIDE)          // 4608
#define W_FLOATS    (32 * SW_STRIDE)           // 4352
#define BUF_FLOATS  (A_FLOATS + 2 * W_FLOATS)  // 13312
#define NBUF        3
#define DYN_BYTES   (NBUF * BUF_FLOATS * 4)    // 159744

// ---------------- device scratch ----------------
__device__ float g_Wg_pad[2 * HIDDEN * CP];    // [512][128] k-major, tf32-rounded
__device__ float g_Wt_pad[HIDDEN * CP];        // [256][128]
__device__ float g_bg_pad[CP];
__device__ float g_bt_pad[CP];
__device__ int   g_start[NUM_GRAPHS + 1];
__device__ float g_readout[NUM_GRAPHS * NUM_CLASSES];

// ---------------- small PTX helpers (all portable, no 'a' features) ----------------
__device__ __forceinline__ uint32_t cvt_tf32(float v) {
    uint32_t o;
    asm("cvt.rna.tf32.f32 %0, %1;" : "=r"(o) : "f"(v));
    return o;
}
__device__ __forceinline__ void cp16(uint32_t dst_smem, const float* src) {
    asm volatile("cp.async.cg.shared.global [%0], [%1], 16;" :: "r"(dst_smem), "l"(src));
}
#define CP_COMMIT() asm volatile("cp.async.commit_group;" ::: "memory")
#define CP_WAIT(n)  asm volatile("cp.async.wait_group %0;" :: "n"(n) : "memory")

__device__ __forceinline__ void mma8(float c[4], const uint32_t a[4], uint32_t b0, uint32_t b1) {
    asm volatile(
        "mma.sync.aligned.m16n8k8.row.col.f32.tf32.tf32.f32 "
        "{%0,%1,%2,%3}, {%4,%5,%6,%7}, {%8,%9}, {%0,%1,%2,%3};"
        : "+f"(c[0]), "+f"(c[1]), "+f"(c[2]), "+f"(c[3])
        : "r"(a[0]), "r"(a[1]), "r"(a[2]), "r"(a[3]), "r"(b0), "r"(b1));
}

// ---------------- prep: pad weights to 128 classes, round to tf32 ----------------
__global__ void prep_kernel(const float* __restrict__ Wg, const float* __restrict__ bg,
                            const float* __restrict__ Wt, const float* __restrict__ bt) {
    int i = blockIdx.x * blockDim.x + threadIdx.x;
    if (i < 2 * HIDDEN * CP) {
        int k = i >> 7, c = i & 127;
        float vg = (c < NUM_CLASSES) ? Wg[k * NUM_CLASSES + c] : 0.f;
        g_Wg_pad[i] = __uint_as_float(cvt_tf32(vg));
        if (k < HIDDEN) {
            float vt = (c < NUM_CLASSES) ? Wt[k * NUM_CLASSES + c] : 0.f;
            g_Wt_pad[i] = __uint_as_float(cvt_tf32(vt));
        }
    }
    if (i < CP) {
        g_bg_pad[i] = (i < NUM_CLASSES) ? bg[i] : 0.f;
        g_bt_pad[i] = (i < NUM_CLASSES) ? bt[i] : 0.f;
    }
}

// ---------------- graph segment starts (sorted ids) ----------------
__global__ void starts_kernel(const int* __restrict__ gl, int n) {
    int g = blockIdx.x * blockDim.x + threadIdx.x;
    if (g > NUM_GRAPHS) return;
    int lo = 0, hi = n;
    while (lo < hi) {
        int mid = (lo + hi) >> 1;
        if (gl[mid] < g) lo = mid + 1; else hi = mid;
    }
    g_start[g] = lo;
}

// ---------------- staging: issue cp.async for one K32 stage ----------------
// stage s in [0,16): s<8 -> pass1 (xi, Wg rows s*32)
//                    s>=8 -> pass2 (xf, Wg rows s*32, Wt rows (s-8)*32)
__device__ __forceinline__ void issue_stage(uint32_t smem_u32, int buf, int s, int t0,
                                            const float* __restrict__ xi,
                                            const float* __restrict__ xf, int tid) {
    uint32_t base = smem_u32 + (uint32_t)(buf * BUF_FLOATS) * 4u;
    const float* src = (s < 8) ? xi : xf;
    const int kb = (s & 7) * 32;
    // A: 128 rows x 32 cols = 1024 float4, 2 per thread
    #pragma unroll
    for (int it = 0; it < 2; it++) {
        int idx = it * 512 + tid;
        int r = idx >> 3, q = idx & 7;
        int row = t0 + r; if (row > N_NODES - 1) row = N_NODES - 1;
        cp16(base + (uint32_t)(r * SA_STRIDE + q * 4) * 4u,
             src + (size_t)row * HIDDEN + kb + q * 4);
    }
    // Wg chunk: 32 rows x 128 cols = 1024 float4, 2 per thread
    #pragma unroll
    for (int it = 0; it < 2; it++) {
        int idx = it * 512 + tid;
        int r = idx >> 5, q = idx & 31;
        cp16(base + (uint32_t)(A_FLOATS + r * SW_STRIDE + q * 4) * 4u,
             g_Wg_pad + (s * 32 + r) * CP + q * 4);
    }
    if (s >= 8) {
        #pragma unroll
        for (int it = 0; it < 2; it++) {
            int idx = it * 512 + tid;
            int r = idx >> 5, q = idx & 31;
            cp16(base + (uint32_t)(A_FLOATS + W_FLOATS + r * SW_STRIDE + q * 4) * 4u,
                 g_Wt_pad + ((s - 8) * 32 + r) * CP + q * 4);
        }
    }
}

// ---------------- compute one K32 stage (4 k8 steps) ----------------
__device__ __forceinline__ void compute_stage(const float* __restrict__ B, bool p2,
                                              int rh64, int gid, int tig, int nb,
                                              float accG[4][2][4], float accT[4][2][4]) {
    const float* A  = B;
    const float* Wg = B + A_FLOATS;
    const float* Wt = Wg + W_FLOATS;
    #pragma unroll
    for (int k8 = 0; k8 < 4; k8++) {
        const int kl = k8 * 8;
        uint32_t a[4][4];
        #pragma unroll
        for (int rg = 0; rg < 4; rg++) {
            int r0 = rh64 + rg * 16 + gid;
            a[rg][0] = cvt_tf32(A[r0 * SA_STRIDE + kl + tig]);
            a[rg][1] = cvt_tf32(A[(r0 + 8) * SA_STRIDE + kl + tig]);
            a[rg][2] = cvt_tf32(A[r0 * SA_STRIDE + kl + tig + 4]);
            a[rg][3] = cvt_tf32(A[(r0 + 8) * SA_STRIDE + kl + tig + 4]);
        }
        #pragma unroll
        for (int nt = 0; nt < 2; nt++) {
            const int cb = nb + nt * 8 + gid;
            uint32_t b0 = __float_as_uint(Wg[(kl + tig) * SW_STRIDE + cb]);
            uint32_t b1 = __float_as_uint(Wg[(kl + tig + 4) * SW_STRIDE + cb]);
            #pragma unroll
            for (int rg = 0; rg < 4; rg++) mma8(accG[rg][nt], a[rg], b0, b1);
            if (p2) {
                uint32_t c0 = __float_as_uint(Wt[(kl + tig) * SW_STRIDE + cb]);
                uint32_t c1 = __float_as_uint(Wt[(kl + tig + 4) * SW_STRIDE + cb]);
                #pragma unroll
                for (int rg = 0; rg < 4; rg++) mma8(accT[rg][nt], a[rg], c0, c1);
            }
        }
    }
}

// ---------------- main fused kernel: one block (512 thr) per graph ----------------
__global__ __launch_bounds__(512, 1) void fused_node_tc(
        const float* __restrict__ xi, const float* __restrict__ xf) {
    extern __shared__ float smem[];
    __shared__ float sAcc[CP];

    const int tid  = threadIdx.x;
    const int lane = tid & 31;
    const int wid  = tid >> 5;
    const int gid  = lane >> 2;     // 0..7
    const int tig  = lane & 3;      // 0..3
    const int wc   = wid & 7;       // column warp group
    const int rh   = wid >> 3;      // row half (0/1)
    const int nb   = wc * 16;
    const int rh64 = rh * 64;

    const uint32_t smem_u32 = (uint32_t)__cvta_generic_to_shared(smem);

    const int g = blockIdx.x;
    const int s0 = g_start[g], e = g_start[g + 1];

    if (tid < CP) sAcc[tid] = 0.f;

    // per-thread biases for owned columns
    float bgE[2], bgO[2], btE[2], btO[2];
    #pragma unroll
    for (int nt = 0; nt < 2; nt++) {
        int cE = nb + nt * 8 + 2 * tig;
        bgE[nt] = g_bg_pad[cE]; bgO[nt] = g_bg_pad[cE + 1];
        btE[nt] = g_bt_pad[cE]; btO[nt] = g_bt_pad[cE + 1];
    }
    float sumE[2] = {0.f, 0.f}, sumO[2] = {0.f, 0.f};   // per-graph class sums
    __syncthreads();

    for (int t0 = s0; t0 < e; t0 += 128) {
        float accG[4][2][4], accT[4][2][4];
        #pragma unroll
        for (int rg = 0; rg < 4; rg++)
            #pragma unroll
            for (int nt = 0; nt < 2; nt++)
                #pragma unroll
                for (int j = 0; j < 4; j++) { accG[rg][nt][j] = 0.f; accT[rg][nt][j] = 0.f; }

        // 3-buffer pipeline, prefetch depth 2
        issue_stage(smem_u32, 0, 0, t0, xi, xf, tid); CP_COMMIT();
        issue_stage(smem_u32, 1, 1, t0, xi, xf, tid); CP_COMMIT();
        for (int s = 0; s < 16; s++) {
            if (s + 2 < 16) {
                int nxt = s + 2;
                issue_stage(smem_u32, nxt % NBUF, nxt, t0, xi, xf, tid); CP_COMMIT();
                CP_WAIT(2);
            } else if (s + 2 == 16) {
                CP_WAIT(1);
            } else {
                CP_WAIT(0);
            }
            __syncthreads();
            compute_stage(smem + (s % NBUF) * BUF_FLOATS, s >= 8,
                          rh64, gid, tig, nb, accG, accT);
            __syncthreads();
        }

        // epilogue: sigmoid(gate)*trans, mask tail rows, fold into per-graph sums
        int cnt = e - t0; if (cnt > 128) cnt = 128;
        #pragma unroll
        for (int nt = 0; nt < 2; nt++) {
            #pragma unroll
            for (int rg = 0; rg < 4; rg++) {
                int r0 = rh64 + rg * 16 + gid;
                int r1 = r0 + 8;
                if (r0 < cnt) {
                    float g0 = accG[rg][nt][0] + bgE[nt];
                    float g1 = accG[rg][nt][1] + bgO[nt];
                    float t0v = accT[rg][nt][0] + btE[nt];
                    float t1v = accT[rg][nt][1] + btO[nt];
                    sumE[nt] += t0v * __fdividef(1.f, 1.f + __expf(-g0));
                    sumO[nt] += t1v * __fdividef(1.f, 1.f + __expf(-g1));
                }
                if (r1 < cnt) {
                    float g2 = accG[rg][nt][2] + bgE[nt];
                    float g3 = accG[rg][nt][3] + bgO[nt];
                    float t2v = accT[rg][nt][2] + btE[nt];
                    float t3v = accT[rg][nt][3] + btO[nt];
                    sumE[nt] += t2v * __fdividef(1.f, 1.f + __expf(-g2));
                    sumO[nt] += t3v * __fdividef(1.f, 1.f + __expf(-g3));
                }
            }
        }
    }

    // reduce over the 8 gid lanes (xor masks 4, 8, 16), then across row-half warps
    #pragma unroll
    for (int nt = 0; nt < 2; nt++) {
        float vE = sumE[nt], vO = sumO[nt];
        #pragma unroll
        for (int m = 4; m <= 16; m <<= 1) {
            vE += __shfl_xor_sync(0xffffffffu, vE, m);
            vO += __shfl_xor_sync(0xffffffffu, vO, m);
        }
        if (gid == 0) {
            int cE = nb + nt * 8 + 2 * tig;
            atomicAdd(&sAcc[cE], vE);
            atomicAdd(&sAcc[cE + 1], vO);
        }
    }
    __syncthreads();
    if (tid < NUM_CLASSES) g_readout[g * NUM_CLASSES + tid] = sAcc[tid];
}

// ---------------- BN + MLP: 8 graphs per block, weights cached in smem ----------------
#define GPB 8
__global__ __launch_bounds__(GRAPH_X, 1) void mlp_kernel(
        const float* __restrict__ aux,
        const float* __restrict__ bn_gamma, const float* __restrict__ bn_beta,
        const float* __restrict__ bn_mean,  const float* __restrict__ bn_var,
        const float* __restrict__ W1, const float* __restrict__ b1,
        const float* __restrict__ W2, const float* __restrict__ b2,
        float* __restrict__ out) {
    extern __shared__ float ws[];                 // W1s[106*128] ++ W2s[128*104]
    float* W1s = ws;
    float* W2s = ws + D_IN * GRAPH_X;
    __shared__ float sn[D_IN];
    __shared__ float sh[GRAPH_X];
    __shared__ float ssc[D_IN], ssh[D_IN];

    const int tid = threadIdx.x;
    for (int i = tid; i < D_IN * GRAPH_X; i += GRAPH_X) W1s[i] = W1[i];
    for (int i = tid; i < GRAPH_X * NUM_CLASSES; i += GRAPH_X) W2s[i] = W2[i];
    if (tid < D_IN) {
        float sc = bn_gamma[tid] * rsqrtf(bn_var[tid] + 1e-5f);
        ssc[tid] = sc;
        ssh[tid] = bn_beta[tid] - bn_mean[tid] * sc;
    }
    const float b1v = b1[tid];
    const float b2v = (tid < NUM_CLASSES) ? b2[tid] : 0.f;
    __syncthreads();

    for (int g = blockIdx.x * GPB; g < (blockIdx.x + 1) * GPB; g++) {
        if (tid < D_IN) {
            float vv = (tid < NUM_CLASSES) ? g_readout[g * NUM_CLASSES + tid]
                                           : aux[g * AUX_DIM + (tid - NUM_CLASSES)];
            sn[tid] = vv * ssc[tid] + ssh[tid];
        }
        __syncthreads();
        float acc = b1v;
        #pragma unroll 2
        for (int d = 0; d < D_IN; d++) acc = fmaf(sn[d], W1s[d * GRAPH_X + tid], acc);
        sh[tid] = fmaxf(acc, 0.f);
        __syncthreads();
        if (tid < NUM_CLASSES) {
            float a2 = b2v;
            #pragma unroll 4
            for (int j = 0; j < GRAPH_X; j++) a2 = fmaf(sh[j], W2s[j * NUM_CLASSES + tid], a2);
            out[g * NUM_CLASSES + tid] = a2;
        }
        __syncthreads();
    }
}

// ---------------- launch ----------------
extern "C" void kernel_launch(void* const* d_in, const int* in_sizes, int n_in,
                              void* d_out, int out_size) {
    int o = (n_in > 4 && in_sizes[4] == 1) ? 1 : 0;
    const float* xi  = (const float*)d_in[0];
    const float* xf  = (const float*)d_in[1];
    const float* aux = (const float*)d_in[2];
    const int*   gl  = (const int*)  d_in[3];
    const float* Wg  = (const float*)d_in[4 + o];
    const float* bg  = (const float*)d_in[5 + o];
    const float* Wt  = (const float*)d_in[6 + o];
    const float* bt  = (const float*)d_in[7 + o];
    const float* bn_gamma = (const float*)d_in[8 + o];
    const float* bn_beta  = (const float*)d_in[9 + o];
    const float* bn_mean  = (const float*)d_in[10 + o];
    const float* bn_var   = (const float*)d_in[11 + o];
    const float* W1 = (const float*)d_in[12 + o];
    const float* b1 = (const float*)d_in[13 + o];
    const float* W2 = (const float*)d_in[14 + o];
    const float* b2 = (const float*)d_in[15 + o];
    float* out = (float*)d_out;

    cudaFuncSetAttribute(fused_node_tc, cudaFuncAttributeMaxDynamicSharedMemorySize, DYN_BYTES);
    int mlp_smem = (D_IN * GRAPH_X + GRAPH_X * NUM_CLASSES) * sizeof(float);
    cudaFuncSetAttribute(mlp_kernel, cudaFuncAttributeMaxDynamicSharedMemorySize, mlp_smem);

    prep_kernel<<<(2 * HIDDEN * CP + 255) / 256, 256>>>(Wg, bg, Wt, bt);
    starts_kernel<<<(NUM_GRAPHS + 1 + 255) / 256, 256>>>(gl, N_NODES);
    fused_node_tc<<<NUM_GRAPHS, 512, DYN_BYTES>>>(xi, xf);
    mlp_kernel<<<NUM_GRAPHS / GPB, GRAPH_X, mlp_smem>>>(aux, bn_gamma, bn_beta, bn_mean, bn_var,
                                                        W1, b1, W2, b2, out);
}

// round 8
// speedup vs baseline: 5.4671x; 1.6307x over previous
#include <cuda_runtime.h>
#include <cuda_fp16.h>
#include <cstdint>
#include <math.h>

#define N_NODES     500000
#define HIDDEN      256
#define NUM_CLASSES 104
#define AUX_DIM     2
#define NUM_GRAPHS  2048
#define D_IN        (NUM_CLASSES + AUX_DIM)   // 106
#define GRAPH_X     128
#define CP          128                        // padded class dim

// smem layout (units: halves)
#define WG_ST   520                            // Wg row stride (k), pad 8
#define WT_ST   264                            // Wt row stride
#define AS_ST   40                             // A row stride (32 + pad 8)
#define WG_OFF  0                              // 128*520 = 66560
#define WT_OFF  66560                          // 128*264 = 33792
#define A_OFF   100352
#define A_BUF   (128 * AS_ST)                  // 5120
#define DYN_BYTES ((A_OFF + 2 * A_BUF) * 2)    // 221184 bytes

// ---------------- device scratch ----------------
__device__ __half g_Wg_h[CP * 2 * HIDDEN];     // [128 n][512 k] fp16
__device__ __half g_Wt_h[CP * HIDDEN];         // [128 n][256 k] fp16
__device__ float  g_bg_pad[CP];
__device__ float  g_bt_pad[CP];
__device__ int    g_start[NUM_GRAPHS + 1];
__device__ float  g_readout[NUM_GRAPHS * NUM_CLASSES];

// ---------------- PTX helpers (portable, no 'a' features) ----------------
__device__ __forceinline__ void cp16(uint32_t dst_smem, const void* src) {
    asm volatile("cp.async.cg.shared.global [%0], [%1], 16;" :: "r"(dst_smem), "l"(src));
}
#define CP_COMMIT() asm volatile("cp.async.commit_group;" ::: "memory")
#define CP_WAIT0()  asm volatile("cp.async.wait_group 0;" ::: "memory")

__device__ __forceinline__ uint32_t pack2(float lo, float hi) {
    uint32_t r;
    asm("cvt.rn.f16x2.f32 %0, %1, %2;" : "=r"(r) : "f"(hi), "f"(lo));  // a->hi, b->lo
    return r;
}
__device__ __forceinline__ void mma16(float c[4], const uint32_t a[4], uint32_t b0, uint32_t b1) {
    asm volatile(
        "mma.sync.aligned.m16n8k16.row.col.f32.f16.f16.f32 "
        "{%0,%1,%2,%3}, {%4,%5,%6,%7}, {%8,%9}, {%0,%1,%2,%3};"
        : "+f"(c[0]), "+f"(c[1]), "+f"(c[2]), "+f"(c[3])
        : "r"(a[0]), "r"(a[1]), "r"(a[2]), "r"(a[3]), "r"(b0), "r"(b1));
}

// ---------------- prep: transpose + pad + fp16-convert weights ----------------
__global__ void prep_kernel(const float* __restrict__ Wg, const float* __restrict__ bg,
                            const float* __restrict__ Wt, const float* __restrict__ bt) {
    int i = blockIdx.x * blockDim.x + threadIdx.x;
    if (i < CP * 2 * HIDDEN) {
        int n = i >> 9, k = i & 511;
        g_Wg_h[i] = __float2half_rn((n < NUM_CLASSES) ? Wg[k * NUM_CLASSES + n] : 0.f);
    }
    if (i < CP * HIDDEN) {
        int n = i >> 8, k = i & 255;
        g_Wt_h[i] = __float2half_rn((n < NUM_CLASSES) ? Wt[k * NUM_CLASSES + n] : 0.f);
    }
    if (i < CP) {
        g_bg_pad[i] = (i < NUM_CLASSES) ? bg[i] : 0.f;
        g_bt_pad[i] = (i < NUM_CLASSES) ? bt[i] : 0.f;
    }
}

// ---------------- graph segment starts (sorted ids) ----------------
__global__ void starts_kernel(const int* __restrict__ gl, int n) {
    int g = blockIdx.x * blockDim.x + threadIdx.x;
    if (g > NUM_GRAPHS) return;
    int lo = 0, hi = n;
    while (lo < hi) {
        int mid = (lo + hi) >> 1;
        if (gl[mid] < g) lo = mid + 1; else hi = mid;
    }
    g_start[g] = lo;
}

// ---------------- main fused kernel: one block (512 thr) per graph ----------------
__global__ __launch_bounds__(512, 1) void fused_node_tc(
        const float* __restrict__ xi, const float* __restrict__ xf) {
    extern __shared__ __half sm[];

    const int tid  = threadIdx.x;
    const int lane = tid & 31;
    const int wid  = tid >> 5;
    const int gid  = lane >> 2;     // 0..7
    const int tig  = lane & 3;      // 0..3
    const int wc   = wid & 7;       // column warp group
    const int rh   = wid >> 3;      // row half (0/1)
    const int nb   = wc * 16;
    const int rh64 = rh * 64;

    const uint32_t smu = (uint32_t)__cvta_generic_to_shared(sm);
    const uint32_t* const U = (const uint32_t*)sm;

    // ---- load ALL weights into smem once (cp.async fp16) ----
    #pragma unroll
    for (int i = 0; i < 16; i++) {
        int idx = i * 512 + tid;
        int n = idx >> 6, kq = idx & 63;
        cp16(smu + (uint32_t)(WG_OFF + n * WG_ST + kq * 8) * 2u, g_Wg_h + n * 512 + kq * 8);
    }
    #pragma unroll
    for (int i = 0; i < 8; i++) {
        int idx = i * 512 + tid;
        int n = idx >> 5, kq = idx & 31;
        cp16(smu + (uint32_t)(WT_OFF + n * WT_ST + kq * 8) * 2u, g_Wt_h + n * 256 + kq * 8);
    }
    CP_COMMIT();

    const int g = blockIdx.x;
    const int s0 = g_start[g], e = g_start[g + 1];

    // per-thread biases for owned columns
    float bgE[2], bgO[2], btE[2], btO[2];
    #pragma unroll
    for (int nt = 0; nt < 2; nt++) {
        int cE = nb + nt * 8 + 2 * tig;
        bgE[nt] = g_bg_pad[cE]; bgO[nt] = g_bg_pad[cE + 1];
        btE[nt] = g_bt_pad[cE]; btO[nt] = g_bt_pad[cE + 1];
    }
    float sumE[2] = {0.f, 0.f}, sumO[2] = {0.f, 0.f};

    const int ar  = tid >> 2;        // A staging: row 0..127
    const int acq = (tid & 3) * 8;   // col chunk (8 floats)

    CP_WAIT0();
    __syncthreads();                 // W resident for all

    for (int t0 = s0; t0 < e; t0 += 128) {
        float accG[4][2][4], accT[4][2][4];
        #pragma unroll
        for (int rg = 0; rg < 4; rg++)
            #pragma unroll
            for (int nt = 0; nt < 2; nt++)
                #pragma unroll
                for (int j = 0; j < 4; j++) { accG[rg][nt][j] = 0.f; accT[rg][nt][j] = 0.f; }

        // prologue: LDG A stage 0 (src=xi, kb=0)
        float4 v0, v1;
        {
            int row = t0 + ar; if (row > N_NODES - 1) row = N_NODES - 1;
            const float* p = xi + (size_t)row * HIDDEN + acq;
            v0 = *(const float4*)p;
            v1 = *(const float4*)(p + 4);
        }

        for (int s = 0; s < 16; s++) {
            // STS stage s (regs -> fp16 smem, double-buffered)
            {
                uint32_t h0 = pack2(v0.x, v0.y), h1 = pack2(v0.z, v0.w);
                uint32_t h2 = pack2(v1.x, v1.y), h3 = pack2(v1.z, v1.w);
                uint32_t d = smu + (uint32_t)(A_OFF + (s & 1) * A_BUF + ar * AS_ST + acq) * 2u;
                asm volatile("st.shared.v4.b32 [%0], {%1,%2,%3,%4};"
                             :: "r"(d), "r"(h0), "r"(h1), "r"(h2), "r"(h3));
            }
            // LDG A stage s+1
            if (s + 1 < 16) {
                int s1 = s + 1;
                const float* src = (s1 < 8) ? xi : xf;
                int kb = (s1 & 7) * 32;
                int row = t0 + ar; if (row > N_NODES - 1) row = N_NODES - 1;
                const float* p = src + (size_t)row * HIDDEN + kb + acq;
                v0 = *(const float4*)p;
                v1 = *(const float4*)(p + 4);
            }
            __syncthreads();

            // ---- compute stage s ----
            const int Ab = A_OFF + (s & 1) * A_BUF;
            const int kg = s * 32;                 // Wg k base (0..511)
            const int kt = (s - 8) * 32;           // Wt k base (pass2)
            const bool p2 = (s >= 8);
            #pragma unroll
            for (int kk = 0; kk < 32; kk += 16) {
                uint32_t a[4][4];
                #pragma unroll
                for (int rg = 0; rg < 4; rg++) {
                    int r0 = rh64 + rg * 16 + gid;
                    int base = Ab + r0 * AS_ST + kk + 2 * tig;
                    a[rg][0] = U[base >> 1];
                    a[rg][1] = U[(base + 8 * AS_ST) >> 1];
                    a[rg][2] = U[(base + 8) >> 1];
                    a[rg][3] = U[(base + 8 * AS_ST + 8) >> 1];
                }
                #pragma unroll
                for (int nt = 0; nt < 2; nt++) {
                    int cb = nb + nt * 8 + gid;
                    int gb = WG_OFF + cb * WG_ST + kg + kk + 2 * tig;
                    uint32_t b0 = U[gb >> 1], b1 = U[(gb + 8) >> 1];
                    #pragma unroll
                    for (int rg = 0; rg < 4; rg++) mma16(accG[rg][nt], a[rg], b0, b1);
                    if (p2) {
                        int tb = WT_OFF + cb * WT_ST + kt + kk + 2 * tig;
                        uint32_t c0 = U[tb >> 1], c1 = U[(tb + 8) >> 1];
                        #pragma unroll
                        for (int rg = 0; rg < 4; rg++) mma16(accT[rg][nt], a[rg], c0, c1);
                    }
                }
            }
        }

        // epilogue: sigmoid(gate)*trans, mask tail rows, fold into per-graph sums
        int cnt = e - t0; if (cnt > 128) cnt = 128;
        #pragma unroll
        for (int nt = 0; nt < 2; nt++) {
            #pragma unroll
            for (int rg = 0; rg < 4; rg++) {
                int r0 = rh64 + rg * 16 + gid;
                int r1 = r0 + 8;
                if (r0 < cnt) {
                    float g0 = accG[rg][nt][0] + bgE[nt];
                    float g1 = accG[rg][nt][1] + bgO[nt];
                    float t0v = accT[rg][nt][0] + btE[nt];
                    float t1v = accT[rg][nt][1] + btO[nt];
                    sumE[nt] += t0v * __fdividef(1.f, 1.f + __expf(-g0));
                    sumO[nt] += t1v * __fdividef(1.f, 1.f + __expf(-g1));
                }
                if (r1 < cnt) {
                    float g2 = accG[rg][nt][2] + bgE[nt];
                    float g3 = accG[rg][nt][3] + bgO[nt];
                    float t2v = accT[rg][nt][2] + btE[nt];
                    float t3v = accT[rg][nt][3] + btO[nt];
                    sumE[nt] += t2v * __fdividef(1.f, 1.f + __expf(-g2));
                    sumO[nt] += t3v * __fdividef(1.f, 1.f + __expf(-g3));
                }
            }
        }
    }

    // ---- final per-graph reduction (sAcc reuses A-buffer smem) ----
    __syncthreads();
    float* sAcc = (float*)(sm + A_OFF);
    if (tid < CP) sAcc[tid] = 0.f;
    __syncthreads();
    #pragma unroll
    for (int nt = 0; nt < 2; nt++) {
        float vE = sumE[nt], vO = sumO[nt];
        #pragma unroll
        for (int m = 4; m <= 16; m <<= 1) {
            vE += __shfl_xor_sync(0xffffffffu, vE, m);
            vO += __shfl_xor_sync(0xffffffffu, vO, m);
        }
        if (gid == 0) {
            int cE = nb + nt * 8 + 2 * tig;
            atomicAdd(&sAcc[cE], vE);
            atomicAdd(&sAcc[cE + 1], vO);
        }
    }
    __syncthreads();
    if (tid < NUM_CLASSES) g_readout[g * NUM_CLASSES + tid] = sAcc[tid];
}

// ---------------- BN + MLP: 2 graphs per block, weights cached in smem ----------------
#define GPB 2
__global__ __launch_bounds__(GRAPH_X, 8) void mlp_kernel(
        const float* __restrict__ aux,
        const float* __restrict__ bn_gamma, const float* __restrict__ bn_beta,
        const float* __restrict__ bn_mean,  const float* __restrict__ bn_var,
        const float* __restrict__ W1, const float* __restrict__ b1,
        const float* __restrict__ W2, const float* __restrict__ b2,
        float* __restrict__ out) {
    extern __shared__ float ws[];                 // W1s[106*128] ++ W2s[128*104]
    float* W1s = ws;
    float* W2s = ws + D_IN * GRAPH_X;
    __shared__ float sn[D_IN];
    __shared__ float sh[GRAPH_X];
    __shared__ float ssc[D_IN], ssh[D_IN];

    const int tid = threadIdx.x;
    for (int i = tid; i < D_IN * GRAPH_X; i += GRAPH_X) W1s[i] = W1[i];
    for (int i = tid; i < GRAPH_X * NUM_CLASSES; i += GRAPH_X) W2s[i] = W2[i];
    if (tid < D_IN) {
        float sc = bn_gamma[tid] * rsqrtf(bn_var[tid] + 1e-5f);
        ssc[tid] = sc;
        ssh[tid] = bn_beta[tid] - bn_mean[tid] * sc;
    }
    const float b1v = b1[tid];
    const float b2v = (tid < NUM_CLASSES) ? b2[tid] : 0.f;
    __syncthreads();

    for (int g = blockIdx.x * GPB; g < (blockIdx.x + 1) * GPB; g++) {
        if (tid < D_IN) {
            float vv = (tid < NUM_CLASSES) ? g_readout[g * NUM_CLASSES + tid]
                                           : aux[g * AUX_DIM + (tid - NUM_CLASSES)];
            sn[tid] = vv * ssc[tid] + ssh[tid];
        }
        __syncthreads();
        float acc = b1v;
        #pragma unroll 2
        for (int d = 0; d < D_IN; d++) acc = fmaf(sn[d], W1s[d * GRAPH_X + tid], acc);
        sh[tid] = fmaxf(acc, 0.f);
        __syncthreads();
        if (tid < NUM_CLASSES) {
            float a2 = b2v;
            #pragma unroll 4
            for (int j = 0; j < GRAPH_X; j++) a2 = fmaf(sh[j], W2s[j * NUM_CLASSES + tid], a2);
            out[g * NUM_CLASSES + tid] = a2;
        }
        __syncthreads();
    }
}

// ---------------- launch ----------------
extern "C" void kernel_launch(void* const* d_in, const int* in_sizes, int n_in,
                              void* d_out, int out_size) {
    int o = (n_in > 4 && in_sizes[4] == 1) ? 1 : 0;
    const float* xi  = (const float*)d_in[0];
    const float* xf  = (const float*)d_in[1];
    const float* aux = (const float*)d_in[2];
    const int*   gl  = (const int*)  d_in[3];
    const float* Wg  = (const float*)d_in[4 + o];
    const float* bg  = (const float*)d_in[5 + o];
    const float* Wt  = (const float*)d_in[6 + o];
    const float* bt  = (const float*)d_in[7 + o];
    const float* bn_gamma = (const float*)d_in[8 + o];
    const float* bn_beta  = (const float*)d_in[9 + o];
    const float* bn_mean  = (const float*)d_in[10 + o];
    const float* bn_var   = (const float*)d_in[11 + o];
    const float* W1 = (const float*)d_in[12 + o];
    const float* b1 = (const float*)d_in[13 + o];
    const float* W2 = (const float*)d_in[14 + o];
    const float* b2 = (const float*)d_in[15 + o];
    float* out = (float*)d_out;

    cudaFuncSetAttribute(fused_node_tc, cudaFuncAttributeMaxDynamicSharedMemorySize, DYN_BYTES);
    int mlp_smem = (D_IN * GRAPH_X + GRAPH_X * NUM_CLASSES) * sizeof(float);
    cudaFuncSetAttribute(mlp_kernel, cudaFuncAttributeMaxDynamicSharedMemorySize, mlp_smem);

    prep_kernel<<<(CP * 2 * HIDDEN + 255) / 256, 256>>>(Wg, bg, Wt, bt);
    starts_kernel<<<(NUM_GRAPHS + 1 + 255) / 256, 256>>>(gl, N_NODES);
    fused_node_tc<<<NUM_GRAPHS, 512, DYN_BYTES>>>(xi, xf);
    mlp_kernel<<<NUM_GRAPHS / GPB, GRAPH_X, mlp_smem>>>(aux, bn_gamma, bn_beta, bn_mean, bn_var,
                                                        W1, b1, W2, b2, out);
}